// round 2
// baseline (speedup 1.0000x reference)
#include <cuda_runtime.h>
#include <cuda_bf16.h>
#include <cstdint>

#define NODES 8192
#define N_ 2048
#define K_ 48
#define H_ 128
#define LDW 136
#define SA_A 280
#define SA_C 408
#define HV_ELEMS (NODES * H_)

__device__ __align__(16) float         g_v1[NODES * H_];
__device__ __align__(16) float         g_f[NODES * 512];
__device__ __align__(16) __nv_bfloat16 g_hvb[NODES * H_];

static __device__ __forceinline__ unsigned su32(const void* p) {
    return (unsigned)__cvta_generic_to_shared(p);
}
static __device__ __forceinline__ float gelu_f(float x) {
    float u = 0.7978845608028654f * (x + 0.044715f * x * x * x), t;
    asm("tanh.approx.f32 %0, %1;" : "=f"(t) : "f"(u));
    return 0.5f * x * (1.0f + t);
}
static __device__ __forceinline__ void load_w(const float* g, __nv_bfloat16* s,
                                              int rows, int tid, int nthr) {
    int total4 = rows * 32;
    for (int i = tid; i < total4; i += nthr) {
        float4 w = ((const float4*)g)[i];
        int r = (i * 4) >> 7, c = (i * 4) & 127;
        *(__nv_bfloat162*)(s + r * LDW + c)     = __floats2bfloat162_rn(w.x, w.y);
        *(__nv_bfloat162*)(s + r * LDW + c + 2) = __floats2bfloat162_rn(w.z, w.w);
    }
}

// C[48x16] += A[48xKD] * W[KDx128] (16 cols starting at ncol0), per-warp.
template <int KD>
static __device__ __forceinline__ void warp_gemm(const __nv_bfloat16* As, int lda,
                                                 const __nv_bfloat16* Ws,
                                                 int ncol0, float acc[3][2][4]) {
    const int lane = threadIdx.x & 31, lr = lane & 15, hi = lane >> 4;
    #pragma unroll
    for (int kt = 0; kt < KD; kt += 16) {
        unsigned a[3][4], b[2][2];
        #pragma unroll
        for (int mt = 0; mt < 3; ++mt) {
            unsigned ad = su32(As + (mt * 16 + lr) * lda + kt + hi * 8);
            asm volatile("ldmatrix.sync.aligned.m8n8.x4.shared.b16 {%0,%1,%2,%3},[%4];"
                         : "=r"(a[mt][0]), "=r"(a[mt][1]), "=r"(a[mt][2]), "=r"(a[mt][3])
                         : "r"(ad));
        }
        #pragma unroll
        for (int nt = 0; nt < 2; ++nt) {
            unsigned ad = su32(Ws + (kt + lr) * LDW + ncol0 + nt * 8);
            asm volatile("ldmatrix.sync.aligned.m8n8.x2.trans.shared.b16 {%0,%1},[%2];"
                         : "=r"(b[nt][0]), "=r"(b[nt][1]) : "r"(ad));
        }
        #pragma unroll
        for (int mt = 0; mt < 3; ++mt)
            #pragma unroll
            for (int nt = 0; nt < 2; ++nt)
                asm volatile("mma.sync.aligned.m16n8k16.row.col.f32.bf16.bf16.f32 "
                             "{%0,%1,%2,%3},{%4,%5,%6,%7},{%8,%9},{%0,%1,%2,%3};"
                             : "+f"(acc[mt][nt][0]), "+f"(acc[mt][nt][1]),
                               "+f"(acc[mt][nt][2]), "+f"(acc[mt][nt][3])
                             : "r"(a[mt][0]), "r"(a[mt][1]), "r"(a[mt][2]), "r"(a[mt][3]),
                               "r"(b[nt][0]), "r"(b[nt][1]));
    }
}
static __device__ __forceinline__ void zero_acc(float acc[3][2][4]) {
    #pragma unroll
    for (int m = 0; m < 3; ++m)
        #pragma unroll
        for (int n = 0; n < 2; ++n)
            #pragma unroll
            for (int i = 0; i < 4; ++i) acc[m][n][i] = 0.0f;
}
static __device__ __forceinline__ void epi_gelu_store(const float acc[3][2][4],
                                                      const float* bias,
                                                      __nv_bfloat16* dst, int lds,
                                                      int ncol0, int lane) {
    int gid = lane >> 2, tig = lane & 3;
    #pragma unroll
    for (int mt = 0; mt < 3; ++mt)
        #pragma unroll
        for (int nt = 0; nt < 2; ++nt) {
            int col = ncol0 + nt * 8 + 2 * tig;
            float b0 = bias[col], b1 = bias[col + 1];
            int r0 = mt * 16 + gid;
            *(__nv_bfloat162*)(dst + r0 * lds + col) = __floats2bfloat162_rn(
                gelu_f(acc[mt][nt][0] + b0), gelu_f(acc[mt][nt][1] + b1));
            *(__nv_bfloat162*)(dst + (r0 + 8) * lds + col) = __floats2bfloat162_rn(
                gelu_f(acc[mt][nt][2] + b0), gelu_f(acc[mt][nt][3] + b1));
        }
}

// ============================ Kernel A ============================
#define SMEM_A_BYTES ((512 * LDW + 48 * SA_A) * 2 + 944 * 4)
__global__ void __launch_bounds__(256, 1)
kA(const float* __restrict__ hV, const float* __restrict__ hE,
   const float* __restrict__ matt,
   const float* __restrict__ W1, const float* __restrict__ b1,
   const float* __restrict__ W2, const float* __restrict__ b2,
   const float* __restrict__ W3, const float* __restrict__ b3,
   const float* __restrict__ g1, const float* __restrict__ bb1) {
    extern __shared__ char smem[];
    __nv_bfloat16* W1s = (__nv_bfloat16*)smem;
    __nv_bfloat16* W2s = W1s + 256 * LDW;
    __nv_bfloat16* W3s = W2s + 128 * LDW;
    __nv_bfloat16* Ab  = W3s + 128 * LDW;
    float* fs   = (float*)(Ab + 48 * SA_A);
    float* hv_s = fs;         float* dh_s = fs + 128;
    float* b1s = fs + 256;    float* b2s = fs + 384;   float* b3s = fs + 512;
    float* mk_s = fs + 640;   float* g1s = fs + 688;   float* bb1s = fs + 816;

    int tid = threadIdx.x, lane = tid & 31, warp = tid >> 5;
    load_w(W1, W1s, 256, tid, 256);
    load_w(W2, W2s, 128, tid, 256);
    load_w(W3, W3s, 128, tid, 256);
    if (tid < 128) {
        b1s[tid] = b1[tid]; b2s[tid] = b2[tid]; b3s[tid] = b3[tid];
        g1s[tid] = g1[tid]; bb1s[tid] = bb1[tid];
    }
    for (int ni = 0; ni < 16; ++ni) {
        int node = blockIdx.x * 16 + ni;
        __syncthreads();
        if (tid < 128) {
            float v = hV[node * H_ + tid];
            hv_s[tid] = v;
            __nv_bfloat16 bv = __float2bfloat16(v);
            #pragma unroll 4
            for (int r = 0; r < 48; ++r) Ab[r * SA_A + tid] = bv;
        }
        if (tid < 48) mk_s[tid] = matt[node * K_ + tid];
        for (int i = tid; i < 48 * 32; i += 256) {
            int k = i >> 5, c = (i & 31) * 4;
            float4 e = *(const float4*)(hE + ((size_t)node * K_ + k) * H_ + c);
            *(__nv_bfloat162*)(Ab + k * SA_A + 128 + c)     = __floats2bfloat162_rn(e.x, e.y);
            *(__nv_bfloat162*)(Ab + k * SA_A + 128 + c + 2) = __floats2bfloat162_rn(e.z, e.w);
        }
        __syncthreads();
        float acc[3][2][4];
        zero_acc(acc);
        warp_gemm<256>(Ab, SA_A, W1s, warp * 16, acc);
        __syncthreads();
        epi_gelu_store(acc, b1s, Ab, SA_A, warp * 16, lane);
        __syncthreads();
        zero_acc(acc);
        warp_gemm<128>(Ab, SA_A, W2s, warp * 16, acc);
        epi_gelu_store(acc, b2s, Ab + 144, SA_A, warp * 16, lane);
        __syncthreads();
        zero_acc(acc);
        warp_gemm<128>(Ab + 144, SA_A, W3s, warp * 16, acc);
        {   // masked sum over K rows
            int gid = lane >> 2, tig = lane & 3;
            float s[2][2] = {{0.f, 0.f}, {0.f, 0.f}};
            #pragma unroll
            for (int mt = 0; mt < 3; ++mt)
                #pragma unroll
                for (int nt = 0; nt < 2; ++nt) {
                    int col = warp * 16 + nt * 8 + 2 * tig;
                    int r0 = mt * 16 + gid;
                    float m0 = mk_s[r0], m1 = mk_s[r0 + 8];
                    s[nt][0] += (acc[mt][nt][0] + b3s[col])     * m0
                              + (acc[mt][nt][2] + b3s[col])     * m1;
                    s[nt][1] += (acc[mt][nt][1] + b3s[col + 1]) * m0
                              + (acc[mt][nt][3] + b3s[col + 1]) * m1;
                }
            #pragma unroll
            for (int off = 4; off < 32; off <<= 1) {
                s[0][0] += __shfl_xor_sync(~0u, s[0][0], off);
                s[0][1] += __shfl_xor_sync(~0u, s[0][1], off);
                s[1][0] += __shfl_xor_sync(~0u, s[1][0], off);
                s[1][1] += __shfl_xor_sync(~0u, s[1][1], off);
            }
            if (lane < 4) {
                dh_s[warp * 16 + 2 * lane]         = s[0][0];
                dh_s[warp * 16 + 2 * lane + 1]     = s[0][1];
                dh_s[warp * 16 + 8 + 2 * lane]     = s[1][0];
                dh_s[warp * 16 + 8 + 2 * lane + 1] = s[1][1];
            }
        }
        __syncthreads();
        if (warp == 0) {   // LN1
            float x[4];
            #pragma unroll
            for (int q = 0; q < 4; ++q)
                x[q] = hv_s[lane * 4 + q] + dh_s[lane * 4 + q] * (1.0f / 30.0f);
            float sm = x[0] + x[1] + x[2] + x[3];
            #pragma unroll
            for (int off = 16; off >= 1; off >>= 1) sm += __shfl_xor_sync(~0u, sm, off);
            float mu = sm * (1.0f / 128.0f), vs = 0.f;
            #pragma unroll
            for (int q = 0; q < 4; ++q) { float d = x[q] - mu; vs += d * d; }
            #pragma unroll
            for (int off = 16; off >= 1; off >>= 1) vs += __shfl_xor_sync(~0u, vs, off);
            float inv = rsqrtf(vs * (1.0f / 128.0f) + 1e-5f);
            #pragma unroll
            for (int q = 0; q < 4; ++q) {
                int c = lane * 4 + q;
                g_v1[node * H_ + c] = (x[q] - mu) * inv * g1s[c] + bb1s[c];
            }
        }
    }
}

// ============================ FFN kernels ============================
#define SMEM_F1_BYTES (128 * 512 * 2 + 768 * 4)
__global__ void __launch_bounds__(512, 1)
kF1(const float* __restrict__ Win, const float* __restrict__ bin) {
    extern __shared__ char smem[];
    __nv_bfloat16* Ws = (__nv_bfloat16*)smem;
    float* bin_s = (float*)(Ws + 128 * 512);
    float* v_s = bin_s + 512;
    int tid = threadIdx.x;
    for (int i = tid; i < 16384; i += 512) {
        float4 w = ((const float4*)Win)[i];
        *(__nv_bfloat162*)(Ws + i * 4)     = __floats2bfloat162_rn(w.x, w.y);
        *(__nv_bfloat162*)(Ws + i * 4 + 2) = __floats2bfloat162_rn(w.z, w.w);
    }
    bin_s[tid] = bin[tid];
    int rowbase = blockIdx.x * 32;
    for (int p = 0; p < 16; ++p) {
        __syncthreads();
        int r0 = rowbase + 2 * p;
        if (tid < 256) v_s[tid] = g_v1[(size_t)(r0 + (tid >> 7)) * H_ + (tid & 127)];
        __syncthreads();
        float a0 = bin_s[tid], a1 = a0;
        #pragma unroll 8
        for (int d = 0; d < 128; ++d) {
            float w = __bfloat162float(Ws[d * 512 + tid]);
            a0 += v_s[d] * w;
            a1 += v_s[128 + d] * w;
        }
        g_f[(size_t)r0 * 512 + tid]       = gelu_f(a0);
        g_f[(size_t)(r0 + 1) * 512 + tid] = gelu_f(a1);
    }
}

#define SMEM_F2_BYTES (512 * 128 * 2 + (1024 + 256 + 384 + 16) * 4)
__global__ void __launch_bounds__(256, 1)
kF2(const float* __restrict__ Wout, const float* __restrict__ bout,
    const float* __restrict__ g2, const float* __restrict__ bb2,
    const float* __restrict__ maskV, float* __restrict__ outV) {
    extern __shared__ char smem[];
    __nv_bfloat16* Ws = (__nv_bfloat16*)smem;
    float* f_s = (float*)(Ws + 512 * 128);
    float* v_s = f_s + 1024;
    float* bo_s = v_s + 256; float* g2s = bo_s + 128; float* b2s = g2s + 128;
    float* red = b2s + 128;  float* red2 = red + 8;
    int tid = threadIdx.x, lane = tid & 31;
    for (int i = tid; i < 16384; i += 256) {
        float4 w = ((const float4*)Wout)[i];
        *(__nv_bfloat162*)(Ws + i * 4)     = __floats2bfloat162_rn(w.x, w.y);
        *(__nv_bfloat162*)(Ws + i * 4 + 2) = __floats2bfloat162_rn(w.z, w.w);
    }
    if (tid < 128) { bo_s[tid] = bout[tid]; g2s[tid] = g2[tid]; b2s[tid] = bb2[tid]; }
    int rowbase = blockIdx.x * 32;
    int row = tid >> 7, c = tid & 127, wig = (tid >> 5) & 3;
    for (int p = 0; p < 16; ++p) {
        __syncthreads();
        int r0 = rowbase + 2 * p;
        float4 xx = ((const float4*)(g_f + (size_t)(r0 + row) * 512))[c];
        *(float4*)&f_s[row * 512 + c * 4] = xx;
        v_s[row * 128 + c] = g_v1[(size_t)(r0 + row) * H_ + c];
        __syncthreads();
        float acc = bo_s[c];
        #pragma unroll 8
        for (int d = 0; d < 512; ++d)
            acc += f_s[row * 512 + d] * __bfloat162float(Ws[d * 128 + c]);
        float x = v_s[row * 128 + c] + acc;
        float sm = x;
        #pragma unroll
        for (int off = 16; off >= 1; off >>= 1) sm += __shfl_xor_sync(~0u, sm, off);
        if (lane == 0) red[row * 4 + wig] = sm;
        __syncthreads();
        float mu = (red[row * 4] + red[row * 4 + 1] + red[row * 4 + 2] + red[row * 4 + 3])
                   * (1.0f / 128.0f);
        float dv = x - mu, sq = dv * dv;
        #pragma unroll
        for (int off = 16; off >= 1; off >>= 1) sq += __shfl_xor_sync(~0u, sq, off);
        if (lane == 0) red2[row * 4 + wig] = sq;
        __syncthreads();
        float var = (red2[row * 4] + red2[row * 4 + 1] + red2[row * 4 + 2] + red2[row * 4 + 3])
                    * (1.0f / 128.0f);
        int gr = r0 + row;
        float y = (dv * rsqrtf(var + 1e-5f) * g2s[c] + b2s[c]) * maskV[gr];
        outV[(size_t)gr * H_ + c] = y;
        g_hvb[(size_t)gr * H_ + c] = __float2bfloat16(y);
    }
}

// ============================ Kernel C ============================
#define SMEM_C_BYTES ((640 * LDW + 48 * SA_C) * 2 + 704 * 4)
__global__ void __launch_bounds__(256, 1)
kC(const float* __restrict__ hE, const int* __restrict__ Eidx,
   const float* __restrict__ W11, const float* __restrict__ b11,
   const float* __restrict__ W12, const float* __restrict__ b12,
   const float* __restrict__ W13, const float* __restrict__ b13,
   const float* __restrict__ g3, const float* __restrict__ bb3,
   float* __restrict__ outE) {
    extern __shared__ char smem[];
    __nv_bfloat16* W1s = (__nv_bfloat16*)smem;
    __nv_bfloat16* W2s = W1s + 384 * LDW;
    __nv_bfloat16* W3s = W2s + 128 * LDW;
    __nv_bfloat16* Ab  = W3s + 128 * LDW;
    float* X = (float*)Ab;                 // overlay, used after layer 3
    float* fs = (float*)(Ab + 48 * SA_C);
    float* b1s = fs;        float* b2s = fs + 128;  float* b3s = fs + 256;
    float* g3s = fs + 384;  float* bb3s = fs + 512;
    int* idx_s = (int*)(fs + 640);

    int tid = threadIdx.x, lane = tid & 31, warp = tid >> 5;
    load_w(W11, W1s, 384, tid, 256);
    load_w(W12, W2s, 128, tid, 256);
    load_w(W13, W3s, 128, tid, 256);
    if (tid < 128) {
        b1s[tid] = b11[tid]; b2s[tid] = b12[tid]; b3s[tid] = b13[tid];
        g3s[tid] = g3[tid];  bb3s[tid] = bb3[tid];
    }
    for (int ni = 0; ni < 16; ++ni) {
        int node = blockIdx.x * 16 + ni;
        int bbase = (node >> 11) << 11;  // node/N_ * N_
        __syncthreads();
        if (tid < 48) idx_s[tid] = Eidx[node * K_ + tid];
        if (tid < 128) {
            __nv_bfloat16 bv = g_hvb[node * H_ + tid];
            #pragma unroll 4
            for (int r = 0; r < 48; ++r) Ab[r * SA_C + tid] = bv;
        }
        for (int i = tid; i < 48 * 32; i += 256) {
            int k = i >> 5, c = (i & 31) * 4;
            float4 e = *(const float4*)(hE + ((size_t)node * K_ + k) * H_ + c);
            *(__nv_bfloat162*)(Ab + k * SA_C + 128 + c)     = __floats2bfloat162_rn(e.x, e.y);
            *(__nv_bfloat162*)(Ab + k * SA_C + 128 + c + 2) = __floats2bfloat162_rn(e.z, e.w);
        }
        __syncthreads();   // idx_s visible
        for (int i = tid; i < 48 * 64; i += 256) {
            int k = i >> 6, c = (i & 63) * 2;
            int nb = bbase + idx_s[k];
            *(__nv_bfloat162*)(Ab + k * SA_C + 256 + c) =
                *(const __nv_bfloat162*)(g_hvb + (size_t)nb * H_ + c);
        }
        __syncthreads();
        float acc[3][2][4];
        zero_acc(acc);
        warp_gemm<384>(Ab, SA_C, W1s, warp * 16, acc);
        __syncthreads();
        epi_gelu_store(acc, b1s, Ab, SA_C, warp * 16, lane);
        __syncthreads();
        zero_acc(acc);
        warp_gemm<128>(Ab, SA_C, W2s, warp * 16, acc);
        epi_gelu_store(acc, b2s, Ab + 144, SA_C, warp * 16, lane);
        __syncthreads();
        zero_acc(acc);
        warp_gemm<128>(Ab + 144, SA_C, W3s, warp * 16, acc);
        __syncthreads();   // all reads of Ab done before X overlay
        {
            int gid = lane >> 2, tig = lane & 3;
            #pragma unroll
            for (int mt = 0; mt < 3; ++mt)
                #pragma unroll
                for (int nt = 0; nt < 2; ++nt) {
                    int col = warp * 16 + nt * 8 + 2 * tig;
                    int r0 = mt * 16 + gid;
                    X[r0 * 132 + col]           = acc[mt][nt][0] + b3s[col];
                    X[r0 * 132 + col + 1]       = acc[mt][nt][1] + b3s[col + 1];
                    X[(r0 + 8) * 132 + col]     = acc[mt][nt][2] + b3s[col];
                    X[(r0 + 8) * 132 + col + 1] = acc[mt][nt][3] + b3s[col + 1];
                }
        }
        __syncthreads();
        // LN3 over h_E + msg: warp w handles rows w*6 .. w*6+5
        for (int rr = 0; rr < 6; ++rr) {
            int r = warp * 6 + rr;
            const float* ep = hE + ((size_t)node * K_ + r) * H_;
            float x[4];
            #pragma unroll
            for (int q = 0; q < 4; ++q)
                x[q] = ep[lane * 4 + q] + X[r * 132 + lane * 4 + q];
            float sm = x[0] + x[1] + x[2] + x[3];
            #pragma unroll
            for (int off = 16; off >= 1; off >>= 1) sm += __shfl_xor_sync(~0u, sm, off);
            float mu = sm * (1.0f / 128.0f), vs = 0.f;
            #pragma unroll
            for (int q = 0; q < 4; ++q) { float d = x[q] - mu; vs += d * d; }
            #pragma unroll
            for (int off = 16; off >= 1; off >>= 1) vs += __shfl_xor_sync(~0u, vs, off);
            float inv = rsqrtf(vs * (1.0f / 128.0f) + 1e-5f);
            float* op = outE + ((size_t)node * K_ + r) * H_;
            #pragma unroll
            for (int q = 0; q < 4; ++q) {
                int c = lane * 4 + q;
                op[c] = (x[q] - mu) * inv * g3s[c] + bb3s[c];
            }
        }
    }
}

// ============================ launch ============================
extern "C" void kernel_launch(void* const* d_in, const int* in_sizes, int n_in,
                              void* d_out, int out_size) {
    const float* hV   = (const float*)d_in[0];
    const float* hE   = (const float*)d_in[1];
    const float* mV   = (const float*)d_in[2];
    const int*   Eidx = (const int*)d_in[3];
    const float* matt = (const float*)d_in[4];
    const float* W1 = (const float*)d_in[5],  *b1 = (const float*)d_in[6];
    const float* W2 = (const float*)d_in[7],  *b2 = (const float*)d_in[8];
    const float* W3 = (const float*)d_in[9],  *b3 = (const float*)d_in[10];
    const float* W11 = (const float*)d_in[11], *b11 = (const float*)d_in[12];
    const float* W12 = (const float*)d_in[13], *b12 = (const float*)d_in[14];
    const float* W13 = (const float*)d_in[15], *b13 = (const float*)d_in[16];
    const float* Win = (const float*)d_in[17], *bin = (const float*)d_in[18];
    const float* Wout = (const float*)d_in[19], *bout = (const float*)d_in[20];
    const float* g1 = (const float*)d_in[21], *bb1 = (const float*)d_in[22];
    const float* g2 = (const float*)d_in[23], *bb2 = (const float*)d_in[24];
    const float* g3 = (const float*)d_in[25], *bb3 = (const float*)d_in[26];
    float* outV = (float*)d_out;
    float* outE = (float*)d_out + HV_ELEMS;

    static bool configured = false;
    if (!configured) {
        cudaFuncSetAttribute(kA,  cudaFuncAttributeMaxDynamicSharedMemorySize, SMEM_A_BYTES);
        cudaFuncSetAttribute(kF1, cudaFuncAttributeMaxDynamicSharedMemorySize, SMEM_F1_BYTES);
        cudaFuncSetAttribute(kF2, cudaFuncAttributeMaxDynamicSharedMemorySize, SMEM_F2_BYTES);
        cudaFuncSetAttribute(kC,  cudaFuncAttributeMaxDynamicSharedMemorySize, SMEM_C_BYTES);
        configured = true;
    }
    kA<<<NODES / 16, 256, SMEM_A_BYTES>>>(hV, hE, matt, W1, b1, W2, b2, W3, b3, g1, bb1);
    kF1<<<NODES / 32, 512, SMEM_F1_BYTES>>>(Win, bin);
    kF2<<<NODES / 32, 256, SMEM_F2_BYTES>>>(Wout, bout, g2, bb2, mV, outV);
    kC<<<NODES / 16, 256, SMEM_C_BYTES>>>(hE, Eidx, W11, b11, W12, b12, W13, b13,
                                          g3, bb3, outE);
}

// round 3
// speedup vs baseline: 1.4065x; 1.4065x over previous
#include <cuda_runtime.h>
#include <cuda_bf16.h>
#include <cstdint>

#define NODES 8192
#define N_ 2048
#define K_ 48
#define H_ 128
#define LDW 136
#define HV_ELEMS (NODES * H_)

__device__ __align__(16) float         g_v1[NODES * H_];
__device__ __align__(16) __nv_bfloat16 g_fb[NODES * 512];
__device__ __align__(16) __nv_bfloat16 g_hvb[NODES * H_];

static __device__ __forceinline__ unsigned su32(const void* p) {
    return (unsigned)__cvta_generic_to_shared(p);
}
static __device__ __forceinline__ void barx(int id) {
    asm volatile("bar.sync %0, %1;" :: "r"(id), "r"(256) : "memory");
}
static __device__ __forceinline__ float gelu_f(float x) {
    float u = 0.7978845608028654f * (x + 0.044715f * x * x * x), t;
    asm("tanh.approx.f32 %0, %1;" : "=f"(t) : "f"(u));
    return 0.5f * x * (1.0f + t);
}
static __device__ __forceinline__ void load_w(const float* g, __nv_bfloat16* s,
                                              int rows, int tid, int nthr) {
    int total4 = rows * 32;
    for (int i = tid; i < total4; i += nthr) {
        float4 w = ((const float4*)g)[i];
        int r = (i * 4) >> 7, c = (i * 4) & 127;
        *(__nv_bfloat162*)(s + r * LDW + c)     = __floats2bfloat162_rn(w.x, w.y);
        *(__nv_bfloat162*)(s + r * LDW + c + 2) = __floats2bfloat162_rn(w.z, w.w);
    }
}

// C[48x16] += A[48xKD] * W[KDx128] (16 cols at ncol0), one warp.
template <int KD>
static __device__ __forceinline__ void warp_gemm(const __nv_bfloat16* As, int lda,
                                                 const __nv_bfloat16* Ws,
                                                 int ncol0, float acc[3][2][4]) {
    const int lane = threadIdx.x & 31, lr = lane & 15, hi = lane >> 4;
    #pragma unroll
    for (int kt = 0; kt < KD; kt += 16) {
        unsigned a[3][4], b[2][2];
        #pragma unroll
        for (int mt = 0; mt < 3; ++mt) {
            unsigned ad = su32(As + (mt * 16 + lr) * lda + kt + hi * 8);
            asm volatile("ldmatrix.sync.aligned.m8n8.x4.shared.b16 {%0,%1,%2,%3},[%4];"
                         : "=r"(a[mt][0]), "=r"(a[mt][1]), "=r"(a[mt][2]), "=r"(a[mt][3])
                         : "r"(ad));
        }
        #pragma unroll
        for (int nt = 0; nt < 2; ++nt) {
            unsigned ad = su32(Ws + (kt + lr) * LDW + ncol0 + nt * 8);
            asm volatile("ldmatrix.sync.aligned.m8n8.x2.trans.shared.b16 {%0,%1},[%2];"
                         : "=r"(b[nt][0]), "=r"(b[nt][1]) : "r"(ad));
        }
        #pragma unroll
        for (int mt = 0; mt < 3; ++mt)
            #pragma unroll
            for (int nt = 0; nt < 2; ++nt)
                asm volatile("mma.sync.aligned.m16n8k16.row.col.f32.bf16.bf16.f32 "
                             "{%0,%1,%2,%3},{%4,%5,%6,%7},{%8,%9},{%0,%1,%2,%3};"
                             : "+f"(acc[mt][nt][0]), "+f"(acc[mt][nt][1]),
                               "+f"(acc[mt][nt][2]), "+f"(acc[mt][nt][3])
                             : "r"(a[mt][0]), "r"(a[mt][1]), "r"(a[mt][2]), "r"(a[mt][3]),
                               "r"(b[nt][0]), "r"(b[nt][1]));
    }
}
static __device__ __forceinline__ void zero_acc(float acc[3][2][4]) {
    #pragma unroll
    for (int m = 0; m < 3; ++m)
        #pragma unroll
        for (int n = 0; n < 2; ++n)
            #pragma unroll
            for (int i = 0; i < 4; ++i) acc[m][n][i] = 0.0f;
}
static __device__ __forceinline__ void epi_gelu_store(const float acc[3][2][4],
                                                      const float* bias,
                                                      __nv_bfloat16* dst, int lds,
                                                      int ncol0, int lane) {
    int gid = lane >> 2, tig = lane & 3;
    #pragma unroll
    for (int mt = 0; mt < 3; ++mt)
        #pragma unroll
        for (int nt = 0; nt < 2; ++nt) {
            int col = ncol0 + nt * 8 + 2 * tig;
            float b0 = bias[col], b1 = bias[col + 1];
            int r0 = mt * 16 + gid;
            *(__nv_bfloat162*)(dst + r0 * lds + col) = __floats2bfloat162_rn(
                gelu_f(acc[mt][nt][0] + b0), gelu_f(acc[mt][nt][1] + b1));
            *(__nv_bfloat162*)(dst + (r0 + 8) * lds + col) = __floats2bfloat162_rn(
                gelu_f(acc[mt][nt][2] + b0), gelu_f(acc[mt][nt][3] + b1));
        }
}
// per-node fold: bias1p[c] = bq[c] + sum_d hv[d] * Whv[d][c]  (64 threads, 2 cols each)
static __device__ __forceinline__ void fold_bias(int stid, const float* bq,
                                                 const __nv_bfloat16* Whv,
                                                 const float* hv_s, float* bias1p) {
    if (stid < 64) {
        int c2 = stid * 2;
        float a0 = bq[c2], a1 = bq[c2 + 1];
        #pragma unroll 4
        for (int d = 0; d < 128; ++d) {
            __nv_bfloat162 w = *(const __nv_bfloat162*)(Whv + d * LDW + c2);
            float h = hv_s[d];
            a0 += h * __low2float(w);
            a1 += h * __high2float(w);
        }
        bias1p[c2] = a0; bias1p[c2 + 1] = a1;
    }
}

// ============================ Kernel A ============================
// A = h_E only (h_V folded into bias). Weff rows: [W1(128:256) | W2 | W3]
#define SMEM_A_BYTES ((384 * LDW + 128 * LDW + 4 * 48 * 136) * 2 + (512 + 2 * 432) * 4)
__global__ void __launch_bounds__(512, 1)
kA(const float* __restrict__ hV, const float* __restrict__ hE,
   const float* __restrict__ matt,
   const float* __restrict__ W1, const float* __restrict__ b1,
   const float* __restrict__ W2, const float* __restrict__ b2,
   const float* __restrict__ W3, const float* __restrict__ b3,
   const float* __restrict__ g1, const float* __restrict__ bb1) {
    extern __shared__ char smem[];
    __nv_bfloat16* Wa  = (__nv_bfloat16*)smem;        // 384 x LDW
    __nv_bfloat16* Whv = Wa + 384 * LDW;              // 128 x LDW
    __nv_bfloat16* Ab0 = Whv + 128 * LDW;             // 2 x 48x136
    __nv_bfloat16* Mb0 = Ab0 + 2 * 48 * 136;          // 2 x 48x136
    float* fs = (float*)(Mb0 + 2 * 48 * 136);
    float* b2s = fs;        float* b3s = fs + 128;
    float* g1s = fs + 256;  float* bb1s = fs + 384;

    int tid = threadIdx.x, lane = tid & 31, warp = tid >> 5;
    int slot = warp >> 3, swarp = warp & 7, stid = tid & 255;
    int bid = 1 + slot;
    __nv_bfloat16* Abs = Ab0 + slot * 48 * 136;
    __nv_bfloat16* Mbs = Mb0 + slot * 48 * 136;
    float* sf = fs + 512 + slot * 432;
    float* hv_s = sf; float* dh_s = sf + 128; float* bias1p = sf + 256; float* mk_s = sf + 384;

    load_w(W1 + 128 * 128, Wa, 128, tid, 512);
    load_w(W2, Wa + 128 * LDW, 128, tid, 512);
    load_w(W3, Wa + 256 * LDW, 128, tid, 512);
    load_w(W1, Whv, 128, tid, 512);
    if (tid < 128) { b2s[tid] = b2[tid]; b3s[tid] = b3[tid];
                     g1s[tid] = g1[tid]; bb1s[tid] = bb1[tid]; }
    __syncthreads();

    for (int ni = 0; ni < 8; ++ni) {
        int node = blockIdx.x * 16 + slot * 8 + ni;
        barx(bid);
        if (stid < 128) hv_s[stid] = hV[node * H_ + stid];
        if (stid < 48)  mk_s[stid] = matt[node * K_ + stid];
        if (stid >= 128)
            for (int i = stid - 128; i < 48 * 32; i += 128) {
                int k = i >> 5, c = (i & 31) * 4;
                float4 e = *(const float4*)(hE + ((size_t)node * K_ + k) * H_ + c);
                *(__nv_bfloat162*)(Abs + k * 136 + c)     = __floats2bfloat162_rn(e.x, e.y);
                *(__nv_bfloat162*)(Abs + k * 136 + c + 2) = __floats2bfloat162_rn(e.z, e.w);
            }
        barx(bid);
        fold_bias(stid, b1, Whv, hv_s, bias1p);
        barx(bid);
        float acc[3][2][4];
        zero_acc(acc);
        warp_gemm<128>(Abs, 136, Wa, swarp * 16, acc);
        epi_gelu_store(acc, bias1p, Mbs, 136, swarp * 16, lane);
        barx(bid);
        zero_acc(acc);
        warp_gemm<128>(Mbs, 136, Wa + 128 * LDW, swarp * 16, acc);
        epi_gelu_store(acc, b2s, Abs, 136, swarp * 16, lane);
        barx(bid);
        zero_acc(acc);
        warp_gemm<128>(Abs, 136, Wa + 256 * LDW, swarp * 16, acc);
        {   // masked sum over 48 rows
            int gid = lane >> 2, tig = lane & 3;
            float s[2][2] = {{0.f, 0.f}, {0.f, 0.f}};
            #pragma unroll
            for (int mt = 0; mt < 3; ++mt)
                #pragma unroll
                for (int nt = 0; nt < 2; ++nt) {
                    int col = swarp * 16 + nt * 8 + 2 * tig;
                    int r0 = mt * 16 + gid;
                    float m0 = mk_s[r0], m1 = mk_s[r0 + 8];
                    s[nt][0] += (acc[mt][nt][0] + b3s[col])     * m0
                              + (acc[mt][nt][2] + b3s[col])     * m1;
                    s[nt][1] += (acc[mt][nt][1] + b3s[col + 1]) * m0
                              + (acc[mt][nt][3] + b3s[col + 1]) * m1;
                }
            #pragma unroll
            for (int off = 4; off < 32; off <<= 1) {
                s[0][0] += __shfl_xor_sync(~0u, s[0][0], off);
                s[0][1] += __shfl_xor_sync(~0u, s[0][1], off);
                s[1][0] += __shfl_xor_sync(~0u, s[1][0], off);
                s[1][1] += __shfl_xor_sync(~0u, s[1][1], off);
            }
            if (lane < 4) {
                dh_s[swarp * 16 + 2 * lane]         = s[0][0];
                dh_s[swarp * 16 + 2 * lane + 1]     = s[0][1];
                dh_s[swarp * 16 + 8 + 2 * lane]     = s[1][0];
                dh_s[swarp * 16 + 8 + 2 * lane + 1] = s[1][1];
            }
        }
        barx(bid);
        if (swarp == 0) {   // LN1
            float x[4];
            #pragma unroll
            for (int q = 0; q < 4; ++q)
                x[q] = hv_s[lane * 4 + q] + dh_s[lane * 4 + q] * (1.0f / 30.0f);
            float sm = x[0] + x[1] + x[2] + x[3];
            #pragma unroll
            for (int off = 16; off >= 1; off >>= 1) sm += __shfl_xor_sync(~0u, sm, off);
            float mu = sm * (1.0f / 128.0f), vs = 0.f;
            #pragma unroll
            for (int q = 0; q < 4; ++q) { float d = x[q] - mu; vs += d * d; }
            #pragma unroll
            for (int off = 16; off >= 1; off >>= 1) vs += __shfl_xor_sync(~0u, vs, off);
            float inv = rsqrtf(vs * (1.0f / 128.0f) + 1e-5f);
            #pragma unroll
            for (int q = 0; q < 4; ++q) {
                int c = lane * 4 + q;
                g_v1[node * H_ + c] = (x[q] - mu) * inv * g1s[c] + bb1s[c];
            }
        }
    }
}

// ============================ FFN kernels ============================
#define SMEM_F1_BYTES (128 * 512 * 2 + 768 * 4)
__global__ void __launch_bounds__(512, 1)
kF1(const float* __restrict__ Win, const float* __restrict__ bin) {
    extern __shared__ char smem[];
    __nv_bfloat16* Ws = (__nv_bfloat16*)smem;
    float* bin_s = (float*)(Ws + 128 * 512);
    float* v_s = bin_s + 512;
    int tid = threadIdx.x;
    for (int i = tid; i < 16384; i += 512) {
        float4 w = ((const float4*)Win)[i];
        *(__nv_bfloat162*)(Ws + i * 4)     = __floats2bfloat162_rn(w.x, w.y);
        *(__nv_bfloat162*)(Ws + i * 4 + 2) = __floats2bfloat162_rn(w.z, w.w);
    }
    bin_s[tid] = bin[tid];
    int rowbase = blockIdx.x * 32;
    for (int p = 0; p < 16; ++p) {
        __syncthreads();
        int r0 = rowbase + 2 * p;
        if (tid < 256) v_s[tid] = g_v1[(size_t)(r0 + (tid >> 7)) * H_ + (tid & 127)];
        __syncthreads();
        float a0 = bin_s[tid], a1 = a0;
        #pragma unroll 8
        for (int d = 0; d < 128; ++d) {
            float w = __bfloat162float(Ws[d * 512 + tid]);
            a0 += v_s[d] * w;
            a1 += v_s[128 + d] * w;
        }
        g_fb[(size_t)r0 * 512 + tid]       = __float2bfloat16(gelu_f(a0));
        g_fb[(size_t)(r0 + 1) * 512 + tid] = __float2bfloat16(gelu_f(a1));
    }
}

#define SMEM_F2_BYTES (512 * 128 * 2 + (1024 + 256 + 384 + 16) * 4)
__global__ void __launch_bounds__(256, 1)
kF2(const float* __restrict__ Wout, const float* __restrict__ bout,
    const float* __restrict__ g2, const float* __restrict__ bb2,
    const float* __restrict__ maskV, float* __restrict__ outV) {
    extern __shared__ char smem[];
    __nv_bfloat16* Ws = (__nv_bfloat16*)smem;
    float* f_s = (float*)(Ws + 512 * 128);
    float* v_s = f_s + 1024;
    float* bo_s = v_s + 256; float* g2s = bo_s + 128; float* b2s = g2s + 128;
    float* red = b2s + 128;  float* red2 = red + 8;
    int tid = threadIdx.x, lane = tid & 31;
    for (int i = tid; i < 16384; i += 256) {
        float4 w = ((const float4*)Wout)[i];
        *(__nv_bfloat162*)(Ws + i * 4)     = __floats2bfloat162_rn(w.x, w.y);
        *(__nv_bfloat162*)(Ws + i * 4 + 2) = __floats2bfloat162_rn(w.z, w.w);
    }
    if (tid < 128) { bo_s[tid] = bout[tid]; g2s[tid] = g2[tid]; b2s[tid] = bb2[tid]; }
    int rowbase = blockIdx.x * 32;
    int row = tid >> 7, c = tid & 127, wig = (tid >> 5) & 3;
    for (int p = 0; p < 16; ++p) {
        __syncthreads();
        int r0 = rowbase + 2 * p;
        #pragma unroll
        for (int i = tid; i < 512; i += 256) {
            int rr = i >> 8, cc = i & 255;
            __nv_bfloat162 v = ((const __nv_bfloat162*)(g_fb + (size_t)(r0 + rr) * 512))[cc];
            f_s[rr * 512 + 2 * cc]     = __low2float(v);
            f_s[rr * 512 + 2 * cc + 1] = __high2float(v);
        }
        v_s[row * 128 + c] = g_v1[(size_t)(r0 + row) * H_ + c];
        __syncthreads();
        float acc = bo_s[c];
        #pragma unroll 8
        for (int d = 0; d < 512; ++d)
            acc += f_s[row * 512 + d] * __bfloat162float(Ws[d * 128 + c]);
        float x = v_s[row * 128 + c] + acc;
        float sm = x;
        #pragma unroll
        for (int off = 16; off >= 1; off >>= 1) sm += __shfl_xor_sync(~0u, sm, off);
        if (lane == 0) red[row * 4 + wig] = sm;
        __syncthreads();
        float mu = (red[row * 4] + red[row * 4 + 1] + red[row * 4 + 2] + red[row * 4 + 3])
                   * (1.0f / 128.0f);
        float dv = x - mu, sq = dv * dv;
        #pragma unroll
        for (int off = 16; off >= 1; off >>= 1) sq += __shfl_xor_sync(~0u, sq, off);
        if (lane == 0) red2[row * 4 + wig] = sq;
        __syncthreads();
        float var = (red2[row * 4] + red2[row * 4 + 1] + red2[row * 4 + 2] + red2[row * 4 + 3])
                    * (1.0f / 128.0f);
        int gr = r0 + row;
        float y = (dv * rsqrtf(var + 1e-5f) * g2s[c] + b2s[c]) * maskV[gr];
        outV[(size_t)gr * H_ + c] = y;
        g_hvb[(size_t)gr * H_ + c] = __float2bfloat16(y);
    }
}

// ============================ Kernel C ============================
// A = [h_E | nbr] (K=256, h_V folded). Wc rows: [W11(128:384) | W12 | W13]
#define SMEM_C_BYTES ((512 * LDW + 128 * LDW + 2 * 48 * 264) * 2 + 1024 * 4 + 2 * 48 * 4)
__global__ void __launch_bounds__(512, 1)
kC(const float* __restrict__ hE, const int* __restrict__ Eidx,
   const float* __restrict__ hVfin,
   const float* __restrict__ W11, const float* __restrict__ b11,
   const float* __restrict__ W12, const float* __restrict__ b12,
   const float* __restrict__ W13, const float* __restrict__ b13,
   const float* __restrict__ g3, const float* __restrict__ bb3,
   float* __restrict__ outE) {
    extern __shared__ char smem[];
    __nv_bfloat16* Wc   = (__nv_bfloat16*)smem;       // 512 x LDW
    __nv_bfloat16* Whvc = Wc + 512 * LDW;             // 128 x LDW
    __nv_bfloat16* Ab0  = Whvc + 128 * LDW;           // 2 x 48x264
    float* fs = (float*)(Ab0 + 2 * 48 * 264);
    float* b2s = fs;        float* b3s = fs + 128;
    float* g3s = fs + 256;  float* bb3s = fs + 384;
    int*  idx0 = (int*)(fs + 1024);

    int tid = threadIdx.x, lane = tid & 31, warp = tid >> 5;
    int slot = warp >> 3, swarp = warp & 7, stid = tid & 255;
    int bid = 1 + slot;
    __nv_bfloat16* Abs = Ab0 + slot * 48 * 264;
    float* sf = fs + 512 + slot * 256;
    float* hv_s = sf; float* bias1p = sf + 128;
    int* idx_s = idx0 + slot * 48;

    load_w(W11 + 128 * 128, Wc, 256, tid, 512);
    load_w(W12, Wc + 256 * LDW, 128, tid, 512);
    load_w(W13, Wc + 384 * LDW, 128, tid, 512);
    load_w(W11, Whvc, 128, tid, 512);
    if (tid < 128) { b2s[tid] = b12[tid]; b3s[tid] = b13[tid];
                     g3s[tid] = g3[tid];  bb3s[tid] = bb3[tid]; }
    __syncthreads();

    for (int ni = 0; ni < 8; ++ni) {
        int node = blockIdx.x * 16 + slot * 8 + ni;
        int bbase = (node >> 11) << 11;
        barx(bid);
        if (stid < 48)  idx_s[stid] = Eidx[node * K_ + stid];
        if (stid < 128) hv_s[stid] = hVfin[node * H_ + stid];
        if (stid >= 128)
            for (int i = stid - 128; i < 48 * 32; i += 128) {
                int k = i >> 5, c = (i & 31) * 4;
                float4 e = *(const float4*)(hE + ((size_t)node * K_ + k) * H_ + c);
                *(__nv_bfloat162*)(Abs + k * 264 + c)     = __floats2bfloat162_rn(e.x, e.y);
                *(__nv_bfloat162*)(Abs + k * 264 + c + 2) = __floats2bfloat162_rn(e.z, e.w);
            }
        barx(bid);
        fold_bias(stid, b11, Whvc, hv_s, bias1p);
        if (stid >= 128)
            for (int i = stid - 128; i < 48 * 64; i += 128) {
                int k = i >> 6, c = (i & 63) * 2;
                int nb = bbase + idx_s[k];
                *(__nv_bfloat162*)(Abs + k * 264 + 128 + c) =
                    *(const __nv_bfloat162*)(g_hvb + (size_t)nb * H_ + c);
            }
        barx(bid);
        float acc[3][2][4];
        zero_acc(acc);
        warp_gemm<256>(Abs, 264, Wc, swarp * 16, acc);   // layer 1 (reads cols 0..255)
        barx(bid);
        epi_gelu_store(acc, bias1p, Abs, 264, swarp * 16, lane);   // M1 -> cols 0..127
        barx(bid);
        zero_acc(acc);
        warp_gemm<128>(Abs, 264, Wc + 256 * LDW, swarp * 16, acc); // layer 2 reads M1
        epi_gelu_store(acc, b2s, Abs + 136, 264, swarp * 16, lane); // M2 -> cols 136..263
        barx(bid);
        zero_acc(acc);
        warp_gemm<128>(Abs + 136, 264, Wc + 384 * LDW, swarp * 16, acc); // layer 3
        barx(bid);
        {   // X (fp32 msg) overlays Abs rows (bytes 0..511 of each 528B row)
            int gid = lane >> 2, tig = lane & 3;
            #pragma unroll
            for (int mt = 0; mt < 3; ++mt)
                #pragma unroll
                for (int nt = 0; nt < 2; ++nt) {
                    int col = swarp * 16 + nt * 8 + 2 * tig;
                    int r0 = mt * 16 + gid;
                    float* X0 = (float*)(Abs + (size_t)r0 * 264);
                    float* X1 = (float*)(Abs + (size_t)(r0 + 8) * 264);
                    X0[col]     = acc[mt][nt][0] + b3s[col];
                    X0[col + 1] = acc[mt][nt][1] + b3s[col + 1];
                    X1[col]     = acc[mt][nt][2] + b3s[col];
                    X1[col + 1] = acc[mt][nt][3] + b3s[col + 1];
                }
        }
        barx(bid);
        for (int rr = 0; rr < 6; ++rr) {   // LN3: warp w -> rows w*6..w*6+5
            int r = swarp * 6 + rr;
            const float* ep = hE + ((size_t)node * K_ + r) * H_;
            const float* Xr = (const float*)(Abs + (size_t)r * 264);
            float x[4];
            #pragma unroll
            for (int q = 0; q < 4; ++q)
                x[q] = ep[lane * 4 + q] + Xr[lane * 4 + q];
            float sm = x[0] + x[1] + x[2] + x[3];
            #pragma unroll
            for (int off = 16; off >= 1; off >>= 1) sm += __shfl_xor_sync(~0u, sm, off);
            float mu = sm * (1.0f / 128.0f), vs = 0.f;
            #pragma unroll
            for (int q = 0; q < 4; ++q) { float d = x[q] - mu; vs += d * d; }
            #pragma unroll
            for (int off = 16; off >= 1; off >>= 1) vs += __shfl_xor_sync(~0u, vs, off);
            float inv = rsqrtf(vs * (1.0f / 128.0f) + 1e-5f);
            float* op = outE + ((size_t)node * K_ + r) * H_;
            #pragma unroll
            for (int q = 0; q < 4; ++q) {
                int c = lane * 4 + q;
                op[c] = (x[q] - mu) * inv * g3s[c] + bb3s[c];
            }
        }
    }
}

// ============================ launch ============================
extern "C" void kernel_launch(void* const* d_in, const int* in_sizes, int n_in,
                              void* d_out, int out_size) {
    const float* hV   = (const float*)d_in[0];
    const float* hE   = (const float*)d_in[1];
    const float* mV   = (const float*)d_in[2];
    const int*   Eidx = (const int*)d_in[3];
    const float* matt = (const float*)d_in[4];
    const float* W1 = (const float*)d_in[5],  *b1 = (const float*)d_in[6];
    const float* W2 = (const float*)d_in[7],  *b2 = (const float*)d_in[8];
    const float* W3 = (const float*)d_in[9],  *b3 = (const float*)d_in[10];
    const float* W11 = (const float*)d_in[11], *b11 = (const float*)d_in[12];
    const float* W12 = (const float*)d_in[13], *b12 = (const float*)d_in[14];
    const float* W13 = (const float*)d_in[15], *b13 = (const float*)d_in[16];
    const float* Win = (const float*)d_in[17], *bin = (const float*)d_in[18];
    const float* Wout = (const float*)d_in[19], *bout = (const float*)d_in[20];
    const float* g1 = (const float*)d_in[21], *bb1 = (const float*)d_in[22];
    const float* g2 = (const float*)d_in[23], *bb2 = (const float*)d_in[24];
    const float* g3 = (const float*)d_in[25], *bb3 = (const float*)d_in[26];
    float* outV = (float*)d_out;
    float* outE = (float*)d_out + HV_ELEMS;

    static bool configured = false;
    if (!configured) {
        cudaFuncSetAttribute(kA,  cudaFuncAttributeMaxDynamicSharedMemorySize, SMEM_A_BYTES);
        cudaFuncSetAttribute(kF1, cudaFuncAttributeMaxDynamicSharedMemorySize, SMEM_F1_BYTES);
        cudaFuncSetAttribute(kF2, cudaFuncAttributeMaxDynamicSharedMemorySize, SMEM_F2_BYTES);
        cudaFuncSetAttribute(kC,  cudaFuncAttributeMaxDynamicSharedMemorySize, SMEM_C_BYTES);
        configured = true;
    }
    kA<<<NODES / 16, 512, SMEM_A_BYTES>>>(hV, hE, matt, W1, b1, W2, b2, W3, b3, g1, bb1);
    kF1<<<NODES / 32, 512, SMEM_F1_BYTES>>>(Win, bin);
    kF2<<<NODES / 32, 256, SMEM_F2_BYTES>>>(Wout, bout, g2, bb2, mV, outV);
    kC<<<NODES / 16, 512, SMEM_C_BYTES>>>(hE, Eidx, outV, W11, b11, W12, b12, W13, b13,
                                          g3, bb3, outE);
}